// round 5
// baseline (speedup 1.0000x reference)
#include <cuda_runtime.h>

// Swap_18957985644706: channel-group roll permutation — converged config.
// x: (B=32, C=256, H=64, W=64) fp32, row-major.
// out group 0 (c in [0,64)):    x[b, c+64, (h-1)%64, w]
// out group 1 (c in [64,128)):  x[b, c-64, (h+1)%64, w]
// out group 2 (c in [128,192)): x[b, c+64, h, (w-1)%64]
// out group 3 (c in [192,256)): x[b, c-64, h, (w+1)%64]
//
// Measured-best configuration (R2): ILP=4, 256-thread blocks, plain
// LDG.128/STG.128. Sweeps showed ILP=8, streaming cache hints, and
// 512-thread blocks are all neutral-to-negative; at 36.4us kernel time the
// chip moves 268.4 MB = 7.37 TB/s combined, ~92% of HBM spec — the mixed
// read/write ceiling. All memory ops are aligned 128-bit; the +/-1 W-shift
// (groups 2/3) is resolved with one warp shuffle across the 16-lane row
// group instead of misaligned loads. QUARTER = 2^21 lands in the batch bits
// of the linear index so c/h/w4/group and shuffle lanes are shared across
// the 4 chunks per thread.

static constexpr unsigned TOTAL_F4 = 32u * 256u * 64u * 16u;   // 8,388,608 = 2^23
static constexpr unsigned QUARTER  = TOTAL_F4 / 4u;            // 2,097,152 = 2^21
static constexpr unsigned THREADS  = 256u;

__global__ void __launch_bounds__(THREADS) swap_roll_kernel(
    const float4* __restrict__ in, float4* __restrict__ out)
{
    unsigned tid = blockIdx.x * THREADS + threadIdx.x;

    unsigned w4 = tid & 15u;          // float4 index within row (0..15)
    unsigned h  = (tid >> 4) & 63u;
    unsigned c  = (tid >> 10) & 255u;
    unsigned b  = tid >> 18;          // low batch bits (0..7)

    unsigned g = c >> 6;              // group 0..3 (warp-uniform)
    unsigned lane = threadIdx.x & 31u;

    unsigned src_c, src_h;
    if (g == 0u)      { src_c = c + 64u; src_h = (h + 63u) & 63u; }
    else if (g == 1u) { src_c = c - 64u; src_h = (h + 1u)  & 63u; }
    else if (g == 2u) { src_c = c + 64u; src_h = h; }
    else              { src_c = c - 64u; src_h = h; }

    unsigned src = ((b * 256u + src_c) * 64u + src_h) * 16u + w4;

    // Front-batched independent loads (MLP = 4)
    float4 v0 = in[src];
    float4 v1 = in[src +      QUARTER];
    float4 v2 = in[src + 2u * QUARTER];
    float4 v3 = in[src + 3u * QUARTER];

    if (g < 2u) {
        out[tid]                = v0;
        out[tid +      QUARTER] = v1;
        out[tid + 2u * QUARTER] = v2;
        out[tid + 3u * QUARTER] = v3;
    } else if (g == 2u) {
        // out[w] = in[w-1]: {prev.w, v.x, v.y, v.z}; prev = lane-1 within
        // the 16-lane row group (wrap inside the half-warp row).
        unsigned srcLane = (lane & 16u) | ((lane + 15u) & 15u);
        float p0 = __shfl_sync(0xffffffffu, v0.w, (int)srcLane);
        float p1 = __shfl_sync(0xffffffffu, v1.w, (int)srcLane);
        float p2 = __shfl_sync(0xffffffffu, v2.w, (int)srcLane);
        float p3 = __shfl_sync(0xffffffffu, v3.w, (int)srcLane);
        out[tid]                = make_float4(p0, v0.x, v0.y, v0.z);
        out[tid +      QUARTER] = make_float4(p1, v1.x, v1.y, v1.z);
        out[tid + 2u * QUARTER] = make_float4(p2, v2.x, v2.y, v2.z);
        out[tid + 3u * QUARTER] = make_float4(p3, v3.x, v3.y, v3.z);
    } else {
        // out[w] = in[w+1]: {v.y, v.z, v.w, next.x}; next = lane+1 within
        // the 16-lane row group (wrap).
        unsigned srcLane = (lane & 16u) | ((lane + 1u) & 15u);
        float n0 = __shfl_sync(0xffffffffu, v0.x, (int)srcLane);
        float n1 = __shfl_sync(0xffffffffu, v1.x, (int)srcLane);
        float n2 = __shfl_sync(0xffffffffu, v2.x, (int)srcLane);
        float n3 = __shfl_sync(0xffffffffu, v3.x, (int)srcLane);
        out[tid]                = make_float4(v0.y, v0.z, v0.w, n0);
        out[tid +      QUARTER] = make_float4(v1.y, v1.z, v1.w, n1);
        out[tid + 2u * QUARTER] = make_float4(v2.y, v2.z, v2.w, n2);
        out[tid + 3u * QUARTER] = make_float4(v3.y, v3.z, v3.w, n3);
    }
}

extern "C" void kernel_launch(void* const* d_in, const int* in_sizes, int n_in,
                              void* d_out, int out_size)
{
    const float4* in  = (const float4*)d_in[0];
    float4*       out = (float4*)d_out;
    swap_roll_kernel<<<QUARTER / THREADS, THREADS>>>(in, out);
}

// round 6
// speedup vs baseline: 1.0015x; 1.0015x over previous
#include <cuda_runtime.h>

// Swap_18957985644706: channel-group roll permutation — converged config.
// x: (B=32, C=256, H=64, W=64) fp32, row-major.
// out group 0 (c in [0,64)):    x[b, c+64, (h-1)%64, w]
// out group 1 (c in [64,128)):  x[b, c-64, (h+1)%64, w]
// out group 2 (c in [128,192)): x[b, c+64, h, (w-1)%64]
// out group 3 (c in [192,256)): x[b, c-64, h, (w+1)%64]
//
// Measured-best shape (R5): ILP=4, 256-thread blocks, plain LDG.128/STG.128,
// gather-on-load / linear stores. At 35.5us the chip moves 268.4 MB =
// 7.56 TB/s combined — 94.5% of HBM spec. Sweeps showed ILP=8, streaming
// hints, and 512-thread blocks neutral-to-negative. This round adds only
// __launch_bounds__(256, 6) (regs 44 -> <=42) to raise resident CTAs and
// chip-wide outstanding-request depth.
//
// All memory ops are aligned 128-bit; the +/-1 W-shift (groups 2/3) is
// resolved with one warp shuffle across the 16-lane row group instead of
// misaligned loads. QUARTER = 2^21 lands in the batch bits of the linear
// index so c/h/w4/group and shuffle lanes are shared across the 4 chunks.

static constexpr unsigned TOTAL_F4 = 32u * 256u * 64u * 16u;   // 8,388,608 = 2^23
static constexpr unsigned QUARTER  = TOTAL_F4 / 4u;            // 2,097,152 = 2^21
static constexpr unsigned THREADS  = 256u;

__global__ void __launch_bounds__(THREADS, 6) swap_roll_kernel(
    const float4* __restrict__ in, float4* __restrict__ out)
{
    unsigned tid = blockIdx.x * THREADS + threadIdx.x;

    unsigned w4 = tid & 15u;          // float4 index within row (0..15)
    unsigned h  = (tid >> 4) & 63u;
    unsigned c  = (tid >> 10) & 255u;
    unsigned b  = tid >> 18;          // low batch bits (0..7)

    unsigned g = c >> 6;              // group 0..3 (warp-uniform)
    unsigned lane = threadIdx.x & 31u;

    unsigned src_c, src_h;
    if (g == 0u)      { src_c = c + 64u; src_h = (h + 63u) & 63u; }
    else if (g == 1u) { src_c = c - 64u; src_h = (h + 1u)  & 63u; }
    else if (g == 2u) { src_c = c + 64u; src_h = h; }
    else              { src_c = c - 64u; src_h = h; }

    unsigned src = ((b * 256u + src_c) * 64u + src_h) * 16u + w4;

    // Front-batched independent loads (MLP = 4)
    float4 v0 = in[src];
    float4 v1 = in[src +      QUARTER];
    float4 v2 = in[src + 2u * QUARTER];
    float4 v3 = in[src + 3u * QUARTER];

    if (g < 2u) {
        out[tid]                = v0;
        out[tid +      QUARTER] = v1;
        out[tid + 2u * QUARTER] = v2;
        out[tid + 3u * QUARTER] = v3;
    } else if (g == 2u) {
        // out[w] = in[w-1]: {prev.w, v.x, v.y, v.z}; prev = lane-1 within
        // the 16-lane row group (wrap inside the half-warp row).
        unsigned srcLane = (lane & 16u) | ((lane + 15u) & 15u);
        float p0 = __shfl_sync(0xffffffffu, v0.w, (int)srcLane);
        float p1 = __shfl_sync(0xffffffffu, v1.w, (int)srcLane);
        float p2 = __shfl_sync(0xffffffffu, v2.w, (int)srcLane);
        float p3 = __shfl_sync(0xffffffffu, v3.w, (int)srcLane);
        out[tid]                = make_float4(p0, v0.x, v0.y, v0.z);
        out[tid +      QUARTER] = make_float4(p1, v1.x, v1.y, v1.z);
        out[tid + 2u * QUARTER] = make_float4(p2, v2.x, v2.y, v2.z);
        out[tid + 3u * QUARTER] = make_float4(p3, v3.x, v3.y, v3.z);
    } else {
        // out[w] = in[w+1]: {v.y, v.z, v.w, next.x}; next = lane+1 within
        // the 16-lane row group (wrap).
        unsigned srcLane = (lane & 16u) | ((lane + 1u) & 15u);
        float n0 = __shfl_sync(0xffffffffu, v0.x, (int)srcLane);
        float n1 = __shfl_sync(0xffffffffu, v1.x, (int)srcLane);
        float n2 = __shfl_sync(0xffffffffu, v2.x, (int)srcLane);
        float n3 = __shfl_sync(0xffffffffu, v3.x, (int)srcLane);
        out[tid]                = make_float4(v0.y, v0.z, v0.w, n0);
        out[tid +      QUARTER] = make_float4(v1.y, v1.z, v1.w, n1);
        out[tid + 2u * QUARTER] = make_float4(v2.y, v2.z, v2.w, n2);
        out[tid + 3u * QUARTER] = make_float4(v3.y, v3.z, v3.w, n3);
    }
}

extern "C" void kernel_launch(void* const* d_in, const int* in_sizes, int n_in,
                              void* d_out, int out_size)
{
    const float4* in  = (const float4*)d_in[0];
    float4*       out = (float4*)d_out;
    swap_roll_kernel<<<QUARTER / THREADS, THREADS>>>(in, out);
}